// round 1
// baseline (speedup 1.0000x reference)
#include <cuda_runtime.h>
#include <math.h>

#define BB 8
#define TT 1024
#define DD 1024
#define HH 16
#define DHD 64
#define D3 3072

// ---------------- scratch (static device arrays; no runtime allocation) ----------------
__device__ float g_qkv[25165824];   // [B,T,3D]
__device__ float g_GI [25165824];   // [B,T,3D]  x@w_ih^T + b_ih
__device__ float g_S  [134217728];  // [B,H,T,T] attention scores
__device__ float g_ctx[8388608];    // [B,T,D]
__device__ float g_A  [8388608];    // [B,T,D]   attention output
__device__ float g_AG [8388608];    // [B,T,D]   a-part of gate preact (incl. gate_b)
__device__ float g_H  [8192];       // [B,D] hidden state
__device__ float g_H1 [8192];       // [B,D] post-GRU state
__device__ unsigned g_bar;          // grid barrier counter (monotonic)

// ---------------- generic tiled SGEMM: C = scale*(A@op(B)) + bias ----------------
// TB=1: B is [N,K] (row-major, NT).  TB=0: B is [K,N] (row-major, NN).
// batch z = z1*Z2 + z2 with independent strides for each level.
#define GTM 64
#define GTN 64
#define GTK 16

template<bool TB>
__global__ __launch_bounds__(256) void gemm_k(
    const float* __restrict__ A0, int lda, long long sA1, long long sA2,
    const float* __restrict__ B0, int ldb, long long sB1, long long sB2,
    float* __restrict__ C0, int ldc, long long sC1, long long sC2,
    int K, int Z2, const float* __restrict__ bias, float scale)
{
    int z  = blockIdx.z;
    int z1 = z / Z2, z2 = z - z1 * Z2;
    const float* A  = A0 + (long long)z1 * sA1 + (long long)z2 * sA2
                         + (long long)blockIdx.y * GTM * lda;
    const float* Bp = B0 + (long long)z1 * sB1 + (long long)z2 * sB2;
    float*       C  = C0 + (long long)z1 * sC1 + (long long)z2 * sC2
                         + (long long)blockIdx.y * GTM * ldc + blockIdx.x * GTN;
    int n0 = blockIdx.x * GTN;

    __shared__ float As[GTK][GTM + 4];
    __shared__ float Bs[GTK][GTN + 4];
    int t  = threadIdx.x;
    int ty = t >> 4, tx = t & 15;
    float acc[4][4] = {};

    for (int k0 = 0; k0 < K; k0 += GTK) {
        #pragma unroll
        for (int r = 0; r < 4; r++) {
            int i = t + 256 * r; int m = i >> 4, kk = i & 15;
            As[kk][m] = A[(long long)m * lda + k0 + kk];
        }
        if (TB) {
            #pragma unroll
            for (int r = 0; r < 4; r++) {
                int i = t + 256 * r; int n = i >> 4, kk = i & 15;
                Bs[kk][n] = Bp[(long long)(n0 + n) * ldb + k0 + kk];
            }
        } else {
            #pragma unroll
            for (int r = 0; r < 4; r++) {
                int i = t + 256 * r; int kk = i >> 6, n = i & 63;
                Bs[kk][n] = Bp[(long long)(k0 + kk) * ldb + n0 + n];
            }
        }
        __syncthreads();
        #pragma unroll
        for (int kk = 0; kk < GTK; kk++) {
            float a[4], b[4];
            #pragma unroll
            for (int i = 0; i < 4; i++) a[i] = As[kk][ty * 4 + i];
            #pragma unroll
            for (int j = 0; j < 4; j++) b[j] = Bs[kk][tx * 4 + j];
            #pragma unroll
            for (int i = 0; i < 4; i++)
                #pragma unroll
                for (int j = 0; j < 4; j++)
                    acc[i][j] = fmaf(a[i], b[j], acc[i][j]);
        }
        __syncthreads();
    }
    #pragma unroll
    for (int i = 0; i < 4; i++) {
        #pragma unroll
        for (int j = 0; j < 4; j++) {
            int n = tx * 4 + j;
            float v = acc[i][j] * scale;
            if (bias) v += bias[n0 + n];
            C[(long long)(ty * 4 + i) * ldc + n] = v;
        }
    }
}

// ---------------- row softmax over 1024 columns ----------------
__global__ __launch_bounds__(256) void softmax_k(float* __restrict__ S)
{
    long long row = blockIdx.x;
    float* p = S + row * (long long)TT;
    int t = threadIdx.x;
    float v0 = p[t], v1 = p[t + 256], v2 = p[t + 512], v3 = p[t + 768];
    float m = fmaxf(fmaxf(v0, v1), fmaxf(v2, v3));
    __shared__ float sredm[8];
    __shared__ float sreds[8];
    #pragma unroll
    for (int o = 16; o; o >>= 1) m = fmaxf(m, __shfl_xor_sync(0xffffffffu, m, o));
    if ((t & 31) == 0) sredm[t >> 5] = m;
    __syncthreads();
    m = fmaxf(fmaxf(fmaxf(sredm[0], sredm[1]), fmaxf(sredm[2], sredm[3])),
              fmaxf(fmaxf(sredm[4], sredm[5]), fmaxf(sredm[6], sredm[7])));
    v0 = expf(v0 - m); v1 = expf(v1 - m); v2 = expf(v2 - m); v3 = expf(v3 - m);
    float s = (v0 + v1) + (v2 + v3);
    #pragma unroll
    for (int o = 16; o; o >>= 1) s += __shfl_xor_sync(0xffffffffu, s, o);
    if ((t & 31) == 0) sreds[t >> 5] = s;
    __syncthreads();
    s = ((sreds[0] + sreds[1]) + (sreds[2] + sreds[3]))
      + ((sreds[4] + sreds[5]) + (sreds[6] + sreds[7]));
    float inv = 1.f / s;
    p[t] = v0 * inv; p[t + 256] = v1 * inv; p[t + 512] = v2 * inv; p[t + 768] = v3 * inv;
}

// ---------------- state / barrier reset (runs before persistent kernel) ----------------
__global__ void reset_k()
{
    int i = blockIdx.x * blockDim.x + threadIdx.x;
    if (i < BB * DD) g_H[i] = 0.f;
    if (i == 0) g_bar = 0u;
}

// ---------------- persistent recurrent kernel ----------------
#define GBLK 132     // <= SM count on any Blackwell datacenter part; 1 block/SM -> co-resident
#define PTH  512
#define DPB  8       // h-dims owned per block (132*8 = 1056 >= 1024)
#define NR1  (3*DPB) // w_hh rows cached per block
#define NR2  DPB     // gate rows cached per block
#define SROW 1028    // padded smem row stride (floats) for bank-conflict-free access

#define RS_SMEM_FLOATS ((NR1 + NR2) * SROW + BB * SROW + PTH + NR1 * 8 + NR1)
#define RS_SMEM_BYTES  (RS_SMEM_FLOATS * 4)

__device__ __forceinline__ void gsync(unsigned& gen)
{
    __syncthreads();
    __threadfence();
    if (threadIdx.x == 0) {
        gen += GBLK;
        atomicAdd(&g_bar, 1u);
        volatile unsigned* p = &g_bar;
        while (*p < gen) { __nanosleep(32); }
        __threadfence();
    }
    __syncthreads();
}

extern __shared__ float sm[];

__global__ __launch_bounds__(PTH, 1) void recur_k(
    const float* __restrict__ w_hh, const float* __restrict__ b_hh,
    const float* __restrict__ gate_w, float* __restrict__ out)
{
    float* wsm  = sm;                          // (NR1+NR2) rows x SROW
    float* hs   = wsm + (NR1 + NR2) * SROW;    // 8 x SROW  (h, then reused for h1)
    float* part = hs + BB * SROW;              // PTH partial dots
    float* ghs  = part + PTH;                  // NR1*8 gh values
    float* bsm  = ghs + NR1 * 8;               // NR1 b_hh values

    int g = blockIdx.x, t = threadIdx.x;
    int d0 = g * DPB;

    // Cache this block's weight rows in smem for the whole kernel.
    for (int r = 0; r < NR1 + NR2; r++) {
        const float* src = nullptr;
        if (r < NR1) { int c = r / DPB, j = r - c * DPB; int dg = d0 + j;
                       if (dg < DD) src = w_hh + (long long)(c * DD + dg) * DD; }
        else         { int j = r - NR1; int dg = d0 + j;
                       if (dg < DD) src = gate_w + (long long)dg * (2 * DD); }
        if (src) for (int k = t; k < DD; k += PTH) wsm[r * SROW + k] = src[k];
        else     for (int k = t; k < DD; k += PTH) wsm[r * SROW + k] = 0.f;
    }
    if (t < NR1) { int c = t / DPB, j = t - c * DPB; int dg = d0 + j;
                   bsm[t] = (dg < DD) ? b_hh[c * DD + dg] : 0.f; }
    __syncthreads();

    unsigned gen = 0;
    // role precompute
    int b1  = t & 7;
    int rr1 = (t >> 3) % NR1;      // valid for t < 2*NR1*8 = 384
    int kh1 = t / (NR1 * 8);
    int u2  = t % (NR2 * 8);
    int b2  = u2 & 7, d82 = u2 >> 3, kh2 = t / (NR2 * 8);   // valid for t < 128

    for (int tok = 0; tok < TT; tok++) {
        #pragma unroll 1
        for (int s = 0; s < 4; s++) {
            // ---- load h into smem (L2-coherent) ----
            {
                const float4* src4 = (const float4*)g_H;
                for (int i4 = t; i4 < (BB * DD / 4); i4 += PTH) {
                    float4 v = __ldcg(src4 + i4); int e = i4 << 2;
                    *(float4*)&hs[(e >> 10) * SROW + (e & 1023)] = v;
                }
            }
            __syncthreads();
            // ---- phase 1: gh partial dots (K split in halves) ----
            if (t < 2 * NR1 * 8) {
                const float4* w4 = (const float4*)&wsm[rr1 * SROW + kh1 * 512];
                const float4* h4 = (const float4*)&hs [b1  * SROW + kh1 * 512];
                float ax = 0, ay = 0, az = 0, aw = 0;
                #pragma unroll 8
                for (int i = 0; i < 128; i++) {
                    float4 w = w4[i], h = h4[i];
                    ax = fmaf(w.x, h.x, ax); ay = fmaf(w.y, h.y, ay);
                    az = fmaf(w.z, h.z, az); aw = fmaf(w.w, h.w, aw);
                }
                part[t] = (ax + ay) + (az + aw);
            }
            __syncthreads();
            if (t < NR1 * 8) ghs[t] = part[t] + part[t + NR1 * 8] + bsm[rr1];
            __syncthreads();
            // ---- GRU elementwise -> h1 ----
            if (t < DPB * 8) {
                int d8 = t >> 3, b = t & 7; int dg = d0 + d8;
                if (dg < DD) {
                    long long gib = ((long long)(b * TT + tok)) * D3 + dg;
                    float ir = g_GI[gib], iz = g_GI[gib + DD], inn = g_GI[gib + 2 * DD];
                    float hr = ghs[d8 * 8 + b];
                    float hz = ghs[(DPB + d8) * 8 + b];
                    float hn = ghs[(2 * DPB + d8) * 8 + b];
                    float r = 1.f / (1.f + expf(-(ir + hr)));
                    float z = 1.f / (1.f + expf(-(iz + hz)));
                    float n = tanhf(inn + r * hn);
                    float hc = hs[b * SROW + dg];
                    float h1 = (1.f - z) * n + z * hc;
                    __stcg(&g_H1[b * DD + dg], h1);
                }
            }
            gsync(gen);
            // ---- load h1 into smem ----
            {
                const float4* src4 = (const float4*)g_H1;
                for (int i4 = t; i4 < (BB * DD / 4); i4 += PTH) {
                    float4 v = __ldcg(src4 + i4); int e = i4 << 2;
                    *(float4*)&hs[(e >> 10) * SROW + (e & 1023)] = v;
                }
            }
            __syncthreads();
            // ---- phase 2: gate partial dots ----
            if (t < 2 * NR2 * 8) {
                int dg = d0 + d82;
                float ax = 0, ay = 0, az = 0, aw = 0;
                if (dg < DD) {
                    const float4* w4 = (const float4*)&wsm[(NR1 + d82) * SROW + kh2 * 512];
                    const float4* h4 = (const float4*)&hs [b2 * SROW + kh2 * 512];
                    #pragma unroll 8
                    for (int i = 0; i < 128; i++) {
                        float4 w = w4[i], h = h4[i];
                        ax = fmaf(w.x, h.x, ax); ay = fmaf(w.y, h.y, ay);
                        az = fmaf(w.z, h.z, az); aw = fmaf(w.w, h.w, aw);
                    }
                }
                part[t] = (ax + ay) + (az + aw);
            }
            __syncthreads();
            // ---- gate elementwise -> new h (and output at last sub-step) ----
            if (t < NR2 * 8) {
                int d8 = t >> 3, b = t & 7; int dg = d0 + d8;
                if (dg < DD) {
                    float dot = part[t] + part[t + NR2 * 8];
                    long long ai = ((long long)(b * TT + tok)) * DD + dg;
                    float gv  = 1.f / (1.f + expf(-(dot + g_AG[ai])));
                    float h1v = hs[b * SROW + dg];
                    float hnew = gv * h1v + (1.f - gv) * g_A[ai];
                    __stcg(&g_H[b * DD + dg], hnew);
                    if (s == 3) out[ai] = hnew;
                }
            }
            gsync(gen);
        }
    }
}

// ---------------- launch ----------------
extern "C" void kernel_launch(void* const* d_in, const int* in_sizes, int n_in,
                              void* d_out, int out_size)
{
    (void)in_sizes; (void)n_in; (void)out_size;
    const float* x   = (const float*)d_in[0];
    const float* ipw = (const float*)d_in[1];
    const float* ipb = (const float*)d_in[2];
    const float* opw = (const float*)d_in[3];
    const float* opb = (const float*)d_in[4];
    const float* wih = (const float*)d_in[5];
    const float* whh = (const float*)d_in[6];
    const float* bih = (const float*)d_in[7];
    const float* bhh = (const float*)d_in[8];
    const float* gw  = (const float*)d_in[9];
    const float* gb  = (const float*)d_in[10];
    float* out = (float*)d_out;

    float *qkv, *GI, *S, *ctx, *A, *AG;
    cudaGetSymbolAddress((void**)&qkv, g_qkv);
    cudaGetSymbolAddress((void**)&GI,  g_GI);
    cudaGetSymbolAddress((void**)&S,   g_S);
    cudaGetSymbolAddress((void**)&ctx, g_ctx);
    cudaGetSymbolAddress((void**)&A,   g_A);
    cudaGetSymbolAddress((void**)&AG,  g_AG);

    cudaFuncSetAttribute(recur_k, cudaFuncAttributeMaxDynamicSharedMemorySize, RS_SMEM_BYTES);

    dim3 blk(256);
    // 1) qkv = x @ in_proj^T + b            [8192,3072]
    gemm_k<true><<<dim3(D3/64, (BB*TT)/64, 1), blk>>>(
        x, DD, 0, 0, ipw, DD, 0, 0, qkv, D3, 0, 0, DD, 1, ipb, 1.f);
    // 2) GI = x @ w_ih^T + b_ih             [8192,3072]
    gemm_k<true><<<dim3(D3/64, (BB*TT)/64, 1), blk>>>(
        x, DD, 0, 0, wih, DD, 0, 0, GI, D3, 0, 0, DD, 1, bih, 1.f);
    // 3) scores S[b,h] = Q K^T / 8          batched 128x [1024,1024], K=64
    gemm_k<true><<<dim3(TT/64, TT/64, BB*HH), blk>>>(
        qkv,      D3, (long long)TT*D3, 64,
        qkv + DD, D3, (long long)TT*D3, 64,
        S, TT, (long long)HH*TT*TT, (long long)TT*TT,
        DHD, HH, nullptr, 0.125f);
    // 4) softmax rows
    softmax_k<<<BB*HH*TT, 256>>>(S);
    // 5) ctx[b,h] = S @ V                   batched 128x [1024,64], K=1024
    gemm_k<false><<<dim3(1, TT/64, BB*HH), blk>>>(
        S, TT, (long long)HH*TT*TT, (long long)TT*TT,
        qkv + 2*DD, D3, (long long)TT*D3, 64,
        ctx, DD, (long long)TT*DD, 64,
        TT, HH, nullptr, 1.f);
    // 6) A = ctx @ out_proj^T + b           [8192,1024]
    gemm_k<true><<<dim3(DD/64, (BB*TT)/64, 1), blk>>>(
        ctx, DD, 0, 0, opw, DD, 0, 0, A, DD, 0, 0, DD, 1, opb, 1.f);
    // 7) AG = A @ gate_w[:,D:]^T + gate_b   [8192,1024]
    gemm_k<true><<<dim3(DD/64, (BB*TT)/64, 1), blk>>>(
        A, DD, 0, 0, gw + DD, 2*DD, 0, 0, AG, DD, 0, 0, DD, 1, gb, 1.f);
    // 8) reset h state + barrier counter (deterministic across graph replays)
    reset_k<<<(BB*DD + 255)/256, 256>>>();
    // 9) persistent sequential recurrence
    recur_k<<<GBLK, PTH, RS_SMEM_BYTES>>>(whh, bhh, gw, out);
}

// round 2
// speedup vs baseline: 1.4575x; 1.4575x over previous
#include <cuda_runtime.h>
#include <math.h>

#define BB 8
#define TT 1024
#define DD 1024
#define HH 16
#define D3 3072

// ---------------- scratch (static device arrays; no runtime allocation) ----------------
__device__ float g_qkv[25165824];   // [B,T,3D]
__device__ float g_GI [25165824];   // [B,T,3D]  x@w_ih^T + b_ih
__device__ float g_S  [134217728];  // [B,H,T,T] attention scores
__device__ float g_ctx[8388608];    // [B,T,D]
__device__ float g_A  [8388608];    // [B,T,D]   attention output
__device__ float g_AG [8388608];    // [B,T,D]   a-part of gate preact (incl. gate_b)
__device__ float g_H  [8192];       // [B,D] hidden state
__device__ float g_H1 [8192];       // [B,D] post-GRU state
__device__ unsigned g_bar;          // grid barrier counter (monotonic)

// ---------------- 128x128 tiled SGEMM: C = scale*(A@op(B)) + bias ----------------
// TB=1: B is [N,K] row-major (NT).  TB=0: B is [K,N] row-major (NN).
// batch z = z1*Z2 + z2 with independent strides per level.

#define GEMM_LOAD(buf, kofs) do {                                               \
    float4 va = *(const float4*)&A[(long long)ar*lda + (kofs) + aq];            \
    As[buf][aq+0][ar]=va.x; As[buf][aq+1][ar]=va.y;                             \
    As[buf][aq+2][ar]=va.z; As[buf][aq+3][ar]=va.w;                             \
    if constexpr (TB) {                                                         \
      if (TN == 128 || t < 128) {                                               \
        float4 vb = *(const float4*)&Bp[(n0 + ar)*ldb + (kofs) + aq];           \
        Bs[buf][aq+0][ar]=vb.x; Bs[buf][aq+1][ar]=vb.y;                         \
        Bs[buf][aq+2][ar]=vb.z; Bs[buf][aq+3][ar]=vb.w;                         \
      }                                                                         \
    } else {                                                                    \
      if constexpr (TN == 128) {                                                \
        int kk = t >> 5, nn = (t & 31) * 4;                                     \
        *(float4*)&Bs[buf][kk][nn] =                                            \
            *(const float4*)&Bp[(long long)((kofs)+kk)*ldb + n0 + nn];          \
      } else {                                                                  \
        if (t < 128) { int kk = t >> 4, nn = (t & 15) * 4;                      \
          *(float4*)&Bs[buf][kk][nn] =                                          \
              *(const float4*)&Bp[(long long)((kofs)+kk)*ldb + n0 + nn]; }      \
      }                                                                         \
    }                                                                           \
  } while (0)

template<int TN, bool TB>
__global__ __launch_bounds__(256) void gemm_k(
    const float* __restrict__ A0, int lda, long long sA1, long long sA2,
    const float* __restrict__ B0, int ldb, long long sB1, long long sB2,
    float* __restrict__ C0, int ldc, long long sC1, long long sC2,
    int K, int Z2, const float* __restrict__ bias, float scale)
{
    constexpr int NJ = TN / 16;   // 8 or 4
    int z  = blockIdx.z;
    int z1 = z / Z2, z2 = z - z1 * Z2;
    const float* A  = A0 + z1 * sA1 + z2 * sA2 + (long long)blockIdx.y * 128 * lda;
    const float* Bp = B0 + z1 * sB1 + z2 * sB2;
    float*       C  = C0 + z1 * sC1 + z2 * sC2 + (long long)blockIdx.y * 128 * ldc
                         + (long long)blockIdx.x * TN;
    long long n0 = (long long)blockIdx.x * TN;

    __shared__ float As[2][8][128];
    __shared__ float Bs[2][8][TN];
    int t = threadIdx.x, tx = t & 15, ty = t >> 4;
    int ar = t >> 1, aq = (t & 1) * 4;

    float acc[8][NJ];
    #pragma unroll
    for (int i = 0; i < 8; i++)
        #pragma unroll
        for (int j = 0; j < NJ; j++) acc[i][j] = 0.f;

    int nk = K >> 3;
    GEMM_LOAD(0, 0);
    __syncthreads();

    for (int kt = 0; kt < nk; kt++) {
        int cb = kt & 1, nb = cb ^ 1;
        if (kt + 1 < nk) { GEMM_LOAD(nb, (kt + 1) << 3); }
        #pragma unroll
        for (int kk = 0; kk < 8; kk++) {
            float4 a0 = *(const float4*)&As[cb][kk][ty * 4];
            float4 a1 = *(const float4*)&As[cb][kk][ty * 4 + 64];
            float4 b0 = *(const float4*)&Bs[cb][kk][tx * 4];
            float av[8] = {a0.x,a0.y,a0.z,a0.w,a1.x,a1.y,a1.z,a1.w};
            if constexpr (NJ == 8) {
                float4 b1 = *(const float4*)&Bs[cb][kk][tx * 4 + 64];
                float bv[8] = {b0.x,b0.y,b0.z,b0.w,b1.x,b1.y,b1.z,b1.w};
                #pragma unroll
                for (int i = 0; i < 8; i++)
                    #pragma unroll
                    for (int j = 0; j < 8; j++)
                        acc[i][j] = fmaf(av[i], bv[j], acc[i][j]);
            } else {
                float bv[4] = {b0.x,b0.y,b0.z,b0.w};
                #pragma unroll
                for (int i = 0; i < 8; i++)
                    #pragma unroll
                    for (int j = 0; j < 4; j++)
                        acc[i][j] = fmaf(av[i], bv[j], acc[i][j]);
            }
        }
        __syncthreads();
    }

    #pragma unroll
    for (int i = 0; i < 8; i++) {
        int row = (i < 4) ? (ty * 4 + i) : (64 + ty * 4 + (i - 4));
        #pragma unroll
        for (int jh = 0; jh < NJ / 4; jh++) {
            int col = tx * 4 + jh * 64;
            float4 v;
            v.x = acc[i][jh*4+0] * scale; v.y = acc[i][jh*4+1] * scale;
            v.z = acc[i][jh*4+2] * scale; v.w = acc[i][jh*4+3] * scale;
            if (bias) {
                v.x += bias[n0+col]; v.y += bias[n0+col+1];
                v.z += bias[n0+col+2]; v.w += bias[n0+col+3];
            }
            *(float4*)&C[(long long)row * ldc + col] = v;
        }
    }
}

// ---------------- row softmax over 1024 columns ----------------
__global__ __launch_bounds__(256) void softmax_k(float* __restrict__ S)
{
    long long row = blockIdx.x;
    float* p = S + row * (long long)TT;
    int t = threadIdx.x;
    float v0 = p[t], v1 = p[t + 256], v2 = p[t + 512], v3 = p[t + 768];
    float m = fmaxf(fmaxf(v0, v1), fmaxf(v2, v3));
    __shared__ float sredm[8];
    __shared__ float sreds[8];
    #pragma unroll
    for (int o = 16; o; o >>= 1) m = fmaxf(m, __shfl_xor_sync(0xffffffffu, m, o));
    if ((t & 31) == 0) sredm[t >> 5] = m;
    __syncthreads();
    m = fmaxf(fmaxf(fmaxf(sredm[0], sredm[1]), fmaxf(sredm[2], sredm[3])),
              fmaxf(fmaxf(sredm[4], sredm[5]), fmaxf(sredm[6], sredm[7])));
    v0 = expf(v0 - m); v1 = expf(v1 - m); v2 = expf(v2 - m); v3 = expf(v3 - m);
    float s = (v0 + v1) + (v2 + v3);
    #pragma unroll
    for (int o = 16; o; o >>= 1) s += __shfl_xor_sync(0xffffffffu, s, o);
    if ((t & 31) == 0) sreds[t >> 5] = s;
    __syncthreads();
    s = ((sreds[0] + sreds[1]) + (sreds[2] + sreds[3]))
      + ((sreds[4] + sreds[5]) + (sreds[6] + sreds[7]));
    float inv = 1.f / s;
    p[t] = v0 * inv; p[t + 256] = v1 * inv; p[t + 512] = v2 * inv; p[t + 768] = v3 * inv;
}

// ---------------- state / barrier reset ----------------
__global__ void reset_k()
{
    int i = blockIdx.x * blockDim.x + threadIdx.x;
    if (i < BB * DD) g_H[i] = 0.f;
    if (i == 0) g_bar = 0u;
}

// ---------------- persistent recurrent kernel ----------------
#define GBLK 128
#define PTH  512
#define DPB  8
#define HST  10   // smem stride per k (floats); 10 -> conflict-free 64b loads

__device__ __forceinline__ void fma2(unsigned long long& d, unsigned long long a,
                                     unsigned long long b, unsigned long long c)
{
    asm("fma.rn.f32x2 %0, %1, %2, %3;" : "=l"(d) : "l"(a), "l"(b), "l"(c));
}
__device__ __forceinline__ unsigned long long add2(unsigned long long a, unsigned long long b)
{
    unsigned long long d;
    asm("add.rn.f32x2 %0, %1, %2;" : "=l"(d) : "l"(a), "l"(b));
    return d;
}
__device__ __forceinline__ unsigned long long pack2(float x)
{
    unsigned long long d; unsigned u = __float_as_uint(x);
    asm("mov.b64 %0, {%1, %2};" : "=l"(d) : "r"(u), "r"(u));
    return d;
}

__device__ __forceinline__ void gsync(unsigned& gen)
{
    __syncthreads();
    __threadfence();
    if (threadIdx.x == 0) {
        gen += GBLK;
        atomicAdd(&g_bar, 1u);
        volatile unsigned* p = &g_bar;
        while (*p < gen) { __nanosleep(32); }
        __threadfence();
    }
    __syncthreads();
}

__global__ __launch_bounds__(PTH, 1) void recur_k(
    const float* __restrict__ w_hh, const float* __restrict__ b_hh,
    const float* __restrict__ gate_w, float* __restrict__ out)
{
    __shared__ float hs[TT * HST];                 // h (or h1), k-major: hs[d*10 + b]
    __shared__ unsigned long long red2[16][12];    // per-warp partials
    __shared__ float bs1[24];
    float* redf = (float*)red2;                    // warp stride = 24 floats

    int t = threadIdx.x, g = blockIdx.x;
    int d0 = g * DPB;
    int wid = t >> 5, lane = t & 31;

    int rg1 = t >> 6,  kc1 = t & 63;    // phase1: 8 groups x 3 rows, 64 k-chunks of 16
    int rg2 = t >> 7,  kc2 = t & 127;   // phase2: 4 groups x 2 rows, 128 k-chunks of 8
    int ed  = t >> 3,  eb  = t & 7;     // elementwise roles (t<64)
    int dg  = d0 + ed;

    // ---- weights resident in registers for the whole kernel ----
    float w1[3][16];
    #pragma unroll
    for (int r = 0; r < 3; r++) {
        int rho = rg1 * 3 + r;                       // 0..23 -> (c=rho>>3, j=rho&7)
        const float* wr = w_hh + (size_t)((rho >> 3) * DD + d0 + (rho & 7)) * DD;
        #pragma unroll
        for (int i = 0; i < 16; i++) w1[r][i] = wr[i * 64 + kc1];
    }
    float w2[2][8];
    #pragma unroll
    for (int r = 0; r < 2; r++) {
        const float* wr = gate_w + (size_t)(d0 + rg2 * 2 + r) * (2 * DD);
        #pragma unroll
        for (int i = 0; i < 8; i++) w2[r][i] = wr[i * 128 + kc2];
    }
    if (t < 24) bs1[t] = b_hh[(t >> 3) * DD + d0 + (t & 7)];
    __syncthreads();

    unsigned gen = 0;

    for (int tok = 0; tok < TT; tok++) {
        // per-token prefetch (constant across the 4 sub-steps)
        float gir = 0, giz = 0, gin = 0, av = 0, agv = 0;
        if (t < 64) {
            size_t gb = ((size_t)(eb * TT + tok)) * D3 + dg;
            gir = __ldg(&g_GI[gb]); giz = __ldg(&g_GI[gb + DD]); gin = __ldg(&g_GI[gb + 2 * DD]);
            size_t ab = ((size_t)(eb * TT + tok)) * DD + dg;
            av = __ldg(&g_A[ab]); agv = __ldg(&g_AG[ab]);
        }
        #pragma unroll 1
        for (int s = 0; s < 4; s++) {
            // ---- broadcast h into smem (transposed, padded) ----
            for (int idx = t; idx < BB * DD; idx += PTH) {
                int b = idx >> 10, d = idx & 1023;
                hs[d * HST + b] = __ldcg(&g_H[idx]);
            }
            __syncthreads();

            // ---- phase 1: gh = W_hh . h  (f32x2, 3 rows x 4 batch-pairs/thread) ----
            unsigned long long acc[12];
            #pragma unroll
            for (int j = 0; j < 12; j++) acc[j] = 0ull;
            #pragma unroll
            for (int i = 0; i < 16; i++) {
                int k = i * 64 + kc1;
                const unsigned long long* hp = (const unsigned long long*)&hs[k * HST];
                unsigned long long h0 = hp[0], h1 = hp[1], h2 = hp[2], h3 = hp[3];
                #pragma unroll
                for (int r = 0; r < 3; r++) {
                    unsigned long long wd = pack2(w1[r][i]);
                    fma2(acc[r*4+0], h0, wd, acc[r*4+0]);
                    fma2(acc[r*4+1], h1, wd, acc[r*4+1]);
                    fma2(acc[r*4+2], h2, wd, acc[r*4+2]);
                    fma2(acc[r*4+3], h3, wd, acc[r*4+3]);
                }
            }
            #pragma unroll
            for (int o = 16; o; o >>= 1)
                #pragma unroll
                for (int j = 0; j < 12; j++)
                    acc[j] = add2(acc[j], __shfl_xor_sync(0xffffffffu, acc[j], o));
            if (lane == 0) {
                #pragma unroll
                for (int j = 0; j < 12; j++) red2[wid][j] = acc[j];
            }
            __syncthreads();

            // ---- GRU elementwise -> h1 ----
            if (t < 64) {
                float gh[3];
                #pragma unroll
                for (int c = 0; c < 3; c++) {
                    int rho = c * 8 + ed;
                    int rgr = rho / 3, rl = rho - rgr * 3;
                    gh[c] = redf[(rgr * 2) * 24 + rl * 8 + eb]
                          + redf[(rgr * 2 + 1) * 24 + rl * 8 + eb] + bs1[rho];
                }
                float rr = 1.f / (1.f + expf(-(gir + gh[0])));
                float zz = 1.f / (1.f + expf(-(giz + gh[1])));
                float nn = tanhf(gin + rr * gh[2]);
                float hc = hs[dg * HST + eb];
                float h1v = (1.f - zz) * nn + zz * hc;
                __stcg(&g_H1[eb * DD + dg], h1v);
            }
            gsync(gen);

            // ---- broadcast h1 into smem ----
            for (int idx = t; idx < BB * DD; idx += PTH) {
                int b = idx >> 10, d = idx & 1023;
                hs[d * HST + b] = __ldcg(&g_H1[idx]);
            }
            __syncthreads();

            // ---- phase 2: gate dot (2 rows x 4 batch-pairs/thread) ----
            unsigned long long a2[8];
            #pragma unroll
            for (int j = 0; j < 8; j++) a2[j] = 0ull;
            #pragma unroll
            for (int i = 0; i < 8; i++) {
                int k = i * 128 + kc2;
                const unsigned long long* hp = (const unsigned long long*)&hs[k * HST];
                unsigned long long h0 = hp[0], h1 = hp[1], h2 = hp[2], h3 = hp[3];
                #pragma unroll
                for (int r = 0; r < 2; r++) {
                    unsigned long long wd = pack2(w2[r][i]);
                    fma2(a2[r*4+0], h0, wd, a2[r*4+0]);
                    fma2(a2[r*4+1], h1, wd, a2[r*4+1]);
                    fma2(a2[r*4+2], h2, wd, a2[r*4+2]);
                    fma2(a2[r*4+3], h3, wd, a2[r*4+3]);
                }
            }
            #pragma unroll
            for (int o = 16; o; o >>= 1)
                #pragma unroll
                for (int j = 0; j < 8; j++)
                    a2[j] = add2(a2[j], __shfl_xor_sync(0xffffffffu, a2[j], o));
            if (lane == 0) {
                #pragma unroll
                for (int j = 0; j < 8; j++) red2[wid][j] = a2[j];
            }
            __syncthreads();

            // ---- gate elementwise -> new h (+ output on last sub-step) ----
            if (t < 64) {
                int rgr = ed >> 1, rl = ed & 1;
                float dot = redf[(rgr*4+0) * 24 + rl * 8 + eb]
                          + redf[(rgr*4+1) * 24 + rl * 8 + eb]
                          + redf[(rgr*4+2) * 24 + rl * 8 + eb]
                          + redf[(rgr*4+3) * 24 + rl * 8 + eb];
                float gv  = 1.f / (1.f + expf(-(dot + agv)));
                float h1v = hs[dg * HST + eb];
                float hnew = gv * h1v + (1.f - gv) * av;
                __stcg(&g_H[eb * DD + dg], hnew);
                if (s == 3) out[((size_t)(eb * TT + tok)) * DD + dg] = hnew;
            }
            gsync(gen);
        }
    }
}

// ---------------- launch ----------------
extern "C" void kernel_launch(void* const* d_in, const int* in_sizes, int n_in,
                              void* d_out, int out_size)
{
    (void)in_sizes; (void)n_in; (void)out_size;
    const float* x   = (const float*)d_in[0];
    const float* ipw = (const float*)d_in[1];
    const float* ipb = (const float*)d_in[2];
    const float* opw = (const float*)d_in[3];
    const float* opb = (const float*)d_in[4];
    const float* wih = (const float*)d_in[5];
    const float* whh = (const float*)d_in[6];
    const float* bih = (const float*)d_in[7];
    const float* bhh = (const float*)d_in[8];
    const float* gw  = (const float*)d_in[9];
    const float* gb  = (const float*)d_in[10];
    float* out = (float*)d_out;

    float *qkv, *GI, *S, *ctx, *A, *AG;
    cudaGetSymbolAddress((void**)&qkv, g_qkv);
    cudaGetSymbolAddress((void**)&GI,  g_GI);
    cudaGetSymbolAddress((void**)&S,   g_S);
    cudaGetSymbolAddress((void**)&ctx, g_ctx);
    cudaGetSymbolAddress((void**)&A,   g_A);
    cudaGetSymbolAddress((void**)&AG,  g_AG);

    dim3 blk(256);
    // 1) qkv = x @ in_proj^T + b            [8192,3072]
    gemm_k<128,true><<<dim3(D3/128, (BB*TT)/128, 1), blk>>>(
        x, DD, 0, 0, ipw, DD, 0, 0, qkv, D3, 0, 0, DD, 1, ipb, 1.f);
    // 2) GI = x @ w_ih^T + b_ih             [8192,3072]
    gemm_k<128,true><<<dim3(D3/128, (BB*TT)/128, 1), blk>>>(
        x, DD, 0, 0, wih, DD, 0, 0, GI, D3, 0, 0, DD, 1, bih, 1.f);
    // 3) scores S[b,h] = Q K^T / 8          batched 128x [1024,1024], K=64
    gemm_k<128,true><<<dim3(TT/128, TT/128, BB*HH), blk>>>(
        qkv,      D3, (long long)TT*D3, 64,
        qkv + DD, D3, (long long)TT*D3, 64,
        S, TT, (long long)HH*TT*TT, (long long)TT*TT,
        64, HH, nullptr, 0.125f);
    // 4) softmax rows
    softmax_k<<<BB*HH*TT, 256>>>(S);
    // 5) ctx[b,h] = S @ V                   batched 128x [1024,64], K=1024
    gemm_k<64,false><<<dim3(1, TT/128, BB*HH), blk>>>(
        S, TT, (long long)HH*TT*TT, (long long)TT*TT,
        qkv + 2*DD, D3, (long long)TT*D3, 64,
        ctx, DD, (long long)TT*DD, 64,
        TT, HH, nullptr, 1.f);
    // 6) A = ctx @ out_proj^T + b           [8192,1024]
    gemm_k<128,true><<<dim3(DD/128, (BB*TT)/128, 1), blk>>>(
        ctx, DD, 0, 0, opw, DD, 0, 0, A, DD, 0, 0, DD, 1, opb, 1.f);
    // 7) AG = A @ gate_w[:,D:]^T + gate_b   [8192,1024]
    gemm_k<128,true><<<dim3(DD/128, (BB*TT)/128, 1), blk>>>(
        A, DD, 0, 0, gw + DD, 2*DD, 0, 0, AG, DD, 0, 0, DD, 1, gb, 1.f);
    // 8) reset h state + barrier counter (deterministic across graph replays)
    reset_k<<<(BB*DD + 255)/256, 256>>>();
    // 9) persistent sequential recurrence
    recur_k<<<GBLK, PTH>>>(whh, bhh, gw, out);
}